// round 2
// baseline (speedup 1.0000x reference)
#include <cuda_runtime.h>
#include <cuda_bf16.h>
#include <cstdint>

// Problem constants (fixed for this problem instance)
#define BB   2
#define KK   32
#define CC   256
#define IHW  512
#define OHW  16
#define NCH  (3 + CC)          // 259 output channels per box
#define NPIX (OHW * OHW)       // 256 output pixels per box

__global__ __launch_bounds__(256, 8)
void roialign_kernel(const float* __restrict__ imgs,
                     const float* __restrict__ bboxess,
                     const int*   __restrict__ counts,
                     const float* __restrict__ p2,
                     const float* __restrict__ p3,
                     const float* __restrict__ p4,
                     const float* __restrict__ p5,
                     float*       __restrict__ out)
{
    const int bk  = blockIdx.x;          // 0..B*K-1
    const int b   = bk / KK;
    const int k   = bk % KK;
    const int grp = blockIdx.y;          // 0 = image channels, 1..16 = feature groups
    const int tid = threadIdx.x;         // 0..255 -> one output pixel
    const int oy  = tid >> 4;
    const int ox  = tid & 15;

    float* outBox = out + (size_t)bk * NCH * NPIX;

    const bool valid = (k < __ldg(counts + b));
    if (!valid) {
        if (grp == 0) {
            #pragma unroll
            for (int c = 0; c < 3; ++c) outBox[c * NPIX + tid] = 0.0f;
        } else {
            const int c0 = 3 + (grp - 1) * 16;
            #pragma unroll
            for (int cc = 0; cc < 16; ++cc) outBox[(c0 + cc) * NPIX + tid] = 0.0f;
        }
        return;
    }

    // ---- per-box scalar metadata (computed redundantly by every thread; cheap) ----
    const float by1 = __ldg(bboxess + bk * 4 + 0);
    const float bx1 = __ldg(bboxess + bk * 4 + 1);
    const float by2 = __ldg(bboxess + bk * 4 + 2);
    const float bx2 = __ldg(bboxess + bk * 4 + 3);

    // level selection: round(clip(6 + 0.5*log2(area/(IH*IW)), 2, 5)), round-half-even
    const float area = (by2 - by1) * (bx2 - bx1);
    float lx = 6.0f + 0.5f * log2f(area * (1.0f / ((float)IHW * (float)IHW)));
    lx = fminf(fmaxf(lx, 2.0f), 5.0f);
    const int lvl = (int)rintf(lx);
    const int ph  = IHW >> lvl;                 // feature map h == w at this level
    const float scale = (float)ph / (float)IHW; // exact power of two

    // rounded + clipped integer bbox
    int y1i = min(max((int)rintf(by1), 0), IHW - 1);
    int x1i = min(max((int)rintf(bx1), 0), IHW - 1);
    int y2i = min(max((int)rintf(by2), y1i + 1), IHW);
    int x2i = min(max((int)rintf(bx2), x1i + 1), IHW);

    // ---- tap tables in shared memory ----
    __shared__ int   sRowI[OHW][4];   // p-row element offsets (row * ph)
    __shared__ float sRowW[OHW][4];
    __shared__ int   sColI[OHW][4];   // p-col indices
    __shared__ float sColW[OHW][4];
    __shared__ int   sImgY[OHW][2];
    __shared__ float sImgWY[OHW][2];
    __shared__ int   sImgX[OHW][2];
    __shared__ float sImgWX[OHW][2];

    if (tid < 16) {
        const int o = tid;
        const float sf = (float)(y2i - y1i);
        const float s  = fmaxf(((float)o + 0.5f) * sf / (float)OHW - 0.5f, 0.0f);
        const int   j0 = (int)floorf(s);
        const int   j1 = min(j0 + 1, (y2i - y1i) - 1);
        const float wt = s - (float)j0;
        const int yi[2]  = { y1i + j0, y1i + j1 };
        const float W[2] = { 1.0f - wt, wt };
        #pragma unroll
        for (int a = 0; a < 2; ++a) {
            sImgY[o][a]  = yi[a];
            sImgWY[o][a] = W[a];
            const float sy = fmaxf(((float)yi[a] + 0.5f) * scale - 0.5f, 0.0f);
            const int   q0 = (int)floorf(sy);
            const int   q1 = min(q0 + 1, ph - 1);
            const float wy = sy - (float)q0;
            sRowI[o][2 * a + 0] = q0 * ph;
            sRowI[o][2 * a + 1] = q1 * ph;
            sRowW[o][2 * a + 0] = W[a] * (1.0f - wy);
            sRowW[o][2 * a + 1] = W[a] * wy;
        }
    } else if (tid < 32) {
        const int o = tid - 16;
        const float sf = (float)(x2i - x1i);
        const float s  = fmaxf(((float)o + 0.5f) * sf / (float)OHW - 0.5f, 0.0f);
        const int   j0 = (int)floorf(s);
        const int   j1 = min(j0 + 1, (x2i - x1i) - 1);
        const float wt = s - (float)j0;
        const int xi[2]  = { x1i + j0, x1i + j1 };
        const float W[2] = { 1.0f - wt, wt };
        #pragma unroll
        for (int a = 0; a < 2; ++a) {
            sImgX[o][a]  = xi[a];
            sImgWX[o][a] = W[a];
            const float sx = fmaxf(((float)xi[a] + 0.5f) * scale - 0.5f, 0.0f);
            const int   q0 = (int)floorf(sx);
            const int   q1 = min(q0 + 1, ph - 1);
            const float wx = sx - (float)q0;
            sColI[o][2 * a + 0] = q0;
            sColI[o][2 * a + 1] = q1;
            sColW[o][2 * a + 0] = W[a] * (1.0f - wx);
            sColW[o][2 * a + 1] = W[a] * wx;
        }
    }
    __syncthreads();

    if (grp == 0) {
        // ---- 3 image channels: plain 4-tap bilinear on the full-res image ----
        const int   iy0 = sImgY[oy][0], iy1 = sImgY[oy][1];
        const int   ix0 = sImgX[ox][0], ix1 = sImgX[ox][1];
        const float wy0 = sImgWY[oy][0], wy1 = sImgWY[oy][1];
        const float wx0 = sImgWX[ox][0], wx1 = sImgWX[ox][1];
        const float* ib = imgs + (size_t)b * 3 * IHW * IHW;
        #pragma unroll
        for (int c = 0; c < 3; ++c) {
            const float* pc = ib + (size_t)c * IHW * IHW;
            const float v =
                wy0 * (wx0 * __ldg(pc + iy0 * IHW + ix0) + wx1 * __ldg(pc + iy0 * IHW + ix1)) +
                wy1 * (wx0 * __ldg(pc + iy1 * IHW + ix0) + wx1 * __ldg(pc + iy1 * IHW + ix1));
            outBox[c * NPIX + tid] = v;
        }
    } else {
        // ---- 16 feature channels: separable 4x4-tap gather from level-selected map ----
        const float* P = (lvl == 2) ? p2 : (lvl == 3) ? p3 : (lvl == 4) ? p4 : p5;
        const int hw = ph * ph;

        int   rI[4], cI[4];
        float rW[4], cW[4];
        #pragma unroll
        for (int i = 0; i < 4; ++i) {
            rI[i] = sRowI[oy][i]; rW[i] = sRowW[oy][i];
            cI[i] = sColI[ox][i]; cW[i] = sColW[ox][i];
        }

        const int c0 = (grp - 1) * 16;
        const float* base = P + ((size_t)b * CC + c0) * hw;
        float* outc = outBox + (size_t)(3 + c0) * NPIX + tid;

        #pragma unroll 4
        for (int cc = 0; cc < 16; ++cc) {
            const float* pc = base + (size_t)cc * hw;
            float acc = 0.0f;
            #pragma unroll
            for (int i = 0; i < 4; ++i) {
                const float* pr = pc + rI[i];
                float part = cW[0] * __ldg(pr + cI[0]);
                part = fmaf(cW[1], __ldg(pr + cI[1]), part);
                part = fmaf(cW[2], __ldg(pr + cI[2]), part);
                part = fmaf(cW[3], __ldg(pr + cI[3]), part);
                acc = fmaf(rW[i], part, acc);
            }
            outc[(size_t)cc * NPIX] = acc;
        }
    }
}

extern "C" void kernel_launch(void* const* d_in, const int* in_sizes, int n_in,
                              void* d_out, int out_size)
{
    const float* imgs    = (const float*)d_in[0];
    const float* bboxess = (const float*)d_in[1];
    const int*   counts  = (const int*)  d_in[2];
    const float* p2      = (const float*)d_in[3];
    const float* p3      = (const float*)d_in[4];
    const float* p4      = (const float*)d_in[5];
    const float* p5      = (const float*)d_in[6];
    // d_in[7] = p6 (unused), d_in[8..11] = scalar dims (statically known)

    dim3 grid(BB * KK, 17);
    roialign_kernel<<<grid, 256>>>(imgs, bboxess, counts, p2, p3, p4, p5,
                                   (float*)d_out);
}

// round 3
// speedup vs baseline: 1.8270x; 1.8270x over previous
#include <cuda_runtime.h>
#include <cuda_bf16.h>
#include <cstdint>

#define BB   2
#define KK   32
#define CC   256
#define IHW  512
#define OHW  16
#define NCH  (3 + CC)
#define NPIX (OHW * OHW)

#define MAXSPAN 40          // window span bound (analysis: <= ~36)
#define SSTRIDE 41          // odd stride -> conflict-free-ish banks
#define CHB     4           // channels staged per batch

__global__ __launch_bounds__(256, 6)
void roialign_kernel(const float* __restrict__ imgs,
                     const float* __restrict__ bboxess,
                     const int*   __restrict__ counts,
                     const float* __restrict__ p2,
                     const float* __restrict__ p3,
                     const float* __restrict__ p4,
                     const float* __restrict__ p5,
                     float*       __restrict__ out)
{
    const int bk  = blockIdx.x;          // 0..B*K-1
    const int b   = bk / KK;
    const int k   = bk % KK;
    const int grp = blockIdx.y;          // 0 = image channels, 1..16 = feature groups
    const int tid = threadIdx.x;         // one output pixel
    const int oy  = tid >> 4;
    const int ox  = tid & 15;

    float* outBox = out + (size_t)bk * NCH * NPIX;

    const bool valid = (k < __ldg(counts + b));
    if (!valid) {
        if (grp == 0) {
            #pragma unroll
            for (int c = 0; c < 3; ++c) outBox[c * NPIX + tid] = 0.0f;
        } else {
            const int c0 = 3 + (grp - 1) * 16;
            #pragma unroll
            for (int cc = 0; cc < 16; ++cc) outBox[(c0 + cc) * NPIX + tid] = 0.0f;
        }
        return;
    }

    // ---- per-box scalars ----
    const float by1 = __ldg(bboxess + bk * 4 + 0);
    const float bx1 = __ldg(bboxess + bk * 4 + 1);
    const float by2 = __ldg(bboxess + bk * 4 + 2);
    const float bx2 = __ldg(bboxess + bk * 4 + 3);

    const float area = (by2 - by1) * (bx2 - bx1);
    float lx = 6.0f + 0.5f * log2f(area * (1.0f / ((float)IHW * (float)IHW)));
    lx = fminf(fmaxf(lx, 2.0f), 5.0f);
    const int lvl = (int)rintf(lx);
    const int ph  = IHW >> lvl;
    const float scale = (float)ph / (float)IHW;

    int y1i = min(max((int)rintf(by1), 0), IHW - 1);
    int x1i = min(max((int)rintf(bx1), 0), IHW - 1);
    int y2i = min(max((int)rintf(by2), y1i + 1), IHW);
    int x2i = min(max((int)rintf(bx2), x1i + 1), IHW);

    // ---- tap tables ----
    __shared__ int   sRowIdx[OHW][4];   // feature row index (global)
    __shared__ float sRowW[OHW][4];
    __shared__ int   sColIdx[OHW][4];   // feature col index (global)
    __shared__ float sColW[OHW][4];
    __shared__ int   sImgY[OHW][2];
    __shared__ float sImgWY[OHW][2];
    __shared__ int   sImgX[OHW][2];
    __shared__ float sImgWX[OHW][2];
    __shared__ int   sRowLo, sRowHi, sColLo, sColHi;
    __shared__ float sWin[CHB][MAXSPAN * SSTRIDE];   // 4 x 6.56 KB = 26.2 KB

    if (tid < 16) {
        const int o = tid;
        const float sf = (float)(y2i - y1i);
        const float s  = fmaxf(((float)o + 0.5f) * sf / (float)OHW - 0.5f, 0.0f);
        const int   j0 = (int)floorf(s);
        const int   j1 = min(j0 + 1, (y2i - y1i) - 1);
        const float wt = s - (float)j0;
        const int yi[2]  = { y1i + j0, y1i + j1 };
        const float W[2] = { 1.0f - wt, wt };
        #pragma unroll
        for (int a = 0; a < 2; ++a) {
            sImgY[o][a]  = yi[a];
            sImgWY[o][a] = W[a];
            const float sy = fmaxf(((float)yi[a] + 0.5f) * scale - 0.5f, 0.0f);
            const int   q0 = (int)floorf(sy);
            const int   q1 = min(q0 + 1, ph - 1);
            const float wy = sy - (float)q0;
            sRowIdx[o][2 * a + 0] = q0;
            sRowIdx[o][2 * a + 1] = q1;
            sRowW[o][2 * a + 0] = W[a] * (1.0f - wy);
            sRowW[o][2 * a + 1] = W[a] * wy;
            if (o == 0  && a == 0) sRowLo = q0;
            if (o == 15 && a == 1) sRowHi = q1;
        }
    } else if (tid < 32) {
        const int o = tid - 16;
        const float sf = (float)(x2i - x1i);
        const float s  = fmaxf(((float)o + 0.5f) * sf / (float)OHW - 0.5f, 0.0f);
        const int   j0 = (int)floorf(s);
        const int   j1 = min(j0 + 1, (x2i - x1i) - 1);
        const float wt = s - (float)j0;
        const int xi[2]  = { x1i + j0, x1i + j1 };
        const float W[2] = { 1.0f - wt, wt };
        #pragma unroll
        for (int a = 0; a < 2; ++a) {
            sImgX[o][a]  = xi[a];
            sImgWX[o][a] = W[a];
            const float sx = fmaxf(((float)xi[a] + 0.5f) * scale - 0.5f, 0.0f);
            const int   q0 = (int)floorf(sx);
            const int   q1 = min(q0 + 1, ph - 1);
            const float wx = sx - (float)q0;
            sColIdx[o][2 * a + 0] = q0;
            sColIdx[o][2 * a + 1] = q1;
            sColW[o][2 * a + 0] = W[a] * (1.0f - wx);
            sColW[o][2 * a + 1] = W[a] * wx;
            if (o == 0  && a == 0) sColLo = q0;
            if (o == 15 && a == 1) sColHi = q1;
        }
    }
    __syncthreads();

    if (grp == 0) {
        // ---- 3 image channels: 4-tap bilinear on the full-res image ----
        const int   iy0 = sImgY[oy][0], iy1 = sImgY[oy][1];
        const int   ix0 = sImgX[ox][0], ix1 = sImgX[ox][1];
        const float wy0 = sImgWY[oy][0], wy1 = sImgWY[oy][1];
        const float wx0 = sImgWX[ox][0], wx1 = sImgWX[ox][1];
        const float* ib = imgs + (size_t)b * 3 * IHW * IHW;
        #pragma unroll
        for (int c = 0; c < 3; ++c) {
            const float* pc = ib + (size_t)c * IHW * IHW;
            const float v =
                wy0 * (wx0 * __ldg(pc + iy0 * IHW + ix0) + wx1 * __ldg(pc + iy0 * IHW + ix1)) +
                wy1 * (wx0 * __ldg(pc + iy1 * IHW + ix0) + wx1 * __ldg(pc + iy1 * IHW + ix1));
            outBox[c * NPIX + tid] = v;
        }
        return;
    }

    // ---- 16 feature channels via shared-memory window staging ----
    const float* P = (lvl == 2) ? p2 : (lvl == 3) ? p3 : (lvl == 4) ? p4 : p5;
    const int hw = ph * ph;

    const int rowLo = sRowLo;
    const int colLo = sColLo;
    const int rowSpan = min(sRowHi - rowLo + 1, MAXSPAN);
    const int colSpan = min(sColHi - colLo + 1, MAXSPAN);
    const int nWin = rowSpan * colSpan;

    // per-thread tap offsets (channel-invariant) + weights, in registers
    int   rOff[4], cOff[4];
    float rW[4], cW[4];
    #pragma unroll
    for (int i = 0; i < 4; ++i) {
        rOff[i] = (sRowIdx[oy][i] - rowLo) * SSTRIDE;
        rW[i]   = sRowW[oy][i];
        cOff[i] = sColIdx[ox][i] - colLo;
        cW[i]   = sColW[ox][i];
    }

    const int cg0 = (grp - 1) * 16;                     // first feature channel of group
    const float* gwin = P + ((size_t)b * CC + cg0) * hw + rowLo * ph + colLo;
    float* outg = outBox + (size_t)(3 + cg0) * NPIX + tid;

    for (int cb = 0; cb < 16 / CHB; ++cb) {
        const float* gb = gwin + (size_t)cb * CHB * hw;
        // cooperative coalesced window load for CHB channels
        for (int idx = tid; idx < nWin; idx += 256) {
            const int r = idx / colSpan;
            const int c = idx - r * colSpan;
            const int g = r * ph + c;
            const int s = r * SSTRIDE + c;
            #pragma unroll
            for (int ch = 0; ch < CHB; ++ch)
                sWin[ch][s] = __ldg(gb + (size_t)ch * hw + g);
        }
        __syncthreads();

        #pragma unroll
        for (int ch = 0; ch < CHB; ++ch) {
            const float* sb = sWin[ch];
            float acc = 0.0f;
            #pragma unroll
            for (int i = 0; i < 4; ++i) {
                const float* sr = sb + rOff[i];
                float part = cW[0] * sr[cOff[0]];
                part = fmaf(cW[1], sr[cOff[1]], part);
                part = fmaf(cW[2], sr[cOff[2]], part);
                part = fmaf(cW[3], sr[cOff[3]], part);
                acc = fmaf(rW[i], part, acc);
            }
            outg[(size_t)(cb * CHB + ch) * NPIX] = acc;
        }
        __syncthreads();   // protect sWin before next batch overwrites
    }
}

extern "C" void kernel_launch(void* const* d_in, const int* in_sizes, int n_in,
                              void* d_out, int out_size)
{
    const float* imgs    = (const float*)d_in[0];
    const float* bboxess = (const float*)d_in[1];
    const int*   counts  = (const int*)  d_in[2];
    const float* p2      = (const float*)d_in[3];
    const float* p3      = (const float*)d_in[4];
    const float* p4      = (const float*)d_in[5];
    const float* p5      = (const float*)d_in[6];

    dim3 grid(BB * KK, 17);
    roialign_kernel<<<grid, 256>>>(imgs, bboxess, counts, p2, p3, p4, p5,
                                   (float*)d_out);
}